// round 15
// baseline (speedup 1.0000x reference)
#include <cuda_runtime.h>
#include <cuda_fp16.h>
#include <math.h>

#define NN   50000
#define DH   128
#define DOUT 57
#define TOTE (800000 + NN)
#define NBLK 49            // ceil(50000/1024)
#define NT   782           // row tiles of 64
#define GEMM_GRID 296      // 2 blocks/SM * 148

// -------- scratch (__device__ globals; zero-initialized at load) --------
__device__ uint2  g_hh[NN * 32];   // h in fp16: [N][32] x (2 half2)
__device__ float4 g_t4[NN * 32];   // aggregation output [N,128] fp32
__device__ float  g_as[NN];        // alpha_src per node
__device__ float  g_ad[NN];        // alpha_dst per node
__device__ int    g_deg[NN];       // zero-init; reset to 0 by k_emit each replay
__device__ int    g_off[NN + 1];
__device__ int    g_cur[NN];
__device__ int    g_srcs[TOTE];    // CSR (by dst): src node per edge
__device__ int    g_bsum[NBLK];    // per-block (deg+1) sums

// ---------------- f32x2 packed-FMA helpers (sm_103a) ----------------
__device__ __forceinline__ unsigned long long pack2(float v) {
    unsigned long long r;
    asm("mov.b64 %0, {%1, %1};" : "=l"(r) : "f"(v));
    return r;
}
__device__ __forceinline__ void fma2(unsigned long long& d,
                                     unsigned long long a, unsigned long long b) {
    asm("fma.rn.f32x2 %0, %1, %2, %0;" : "+l"(d) : "l"(a), "l"(b));
}
__device__ __forceinline__ float2 unpack2(unsigned long long v) {
    float x, y;
    asm("mov.b64 {%0, %1}, %2;" : "=f"(x), "=f"(y) : "l"(v));
    return make_float2(x, y);
}

// ---------------- fp16x2 <-> fp32 helpers ----------------
__device__ __forceinline__ unsigned int f2_to_h2(float lo, float hi) {
    unsigned int r;
    asm("cvt.rn.f16x2.f32 %0, %2, %1;" : "=r"(r) : "f"(lo), "f"(hi));
    return r;
}
__device__ __forceinline__ float2 h2_to_f2(unsigned int u) {
    __half2 h = *reinterpret_cast<__half2*>(&u);
    return __half22float2(h);
}

// ---------------- cp.async helpers ----------------
__device__ __forceinline__ void cp_async16(void* smem_dst, const void* gmem_src) {
    unsigned int d = (unsigned int)__cvta_generic_to_shared(smem_dst);
    asm volatile("cp.async.cg.shared.global [%0], [%1], 16;" :: "r"(d), "l"(gmem_src));
}
__device__ __forceinline__ void cp_async_commit() {
    asm volatile("cp.async.commit_group;" ::: "memory");
}
__device__ __forceinline__ void cp_async_wait_all() {
    asm volatile("cp.async.wait_group 0;" ::: "memory");
}

// ============================ CSR build (5 small kernels) ============================
__global__ void k_count(const int* __restrict__ ei, int E) {
    int e4 = blockIdx.x * blockDim.x + threadIdx.x;
    if (e4 * 4 < E) {
        int4 d = ((const int4*)(ei + E))[e4];
        if (d.x >= 0 && d.x < NN) atomicAdd(&g_deg[d.x], 1);
        if (d.y >= 0 && d.y < NN) atomicAdd(&g_deg[d.y], 1);
        if (d.z >= 0 && d.z < NN) atomicAdd(&g_deg[d.z], 1);
        if (d.w >= 0 && d.w < NN) atomicAdd(&g_deg[d.w], 1);
    }
}

__global__ void k_blocksum() {
    __shared__ int red[1024];
    int t = threadIdx.x;
    int idx = blockIdx.x * 1024 + t;
    red[t] = (idx < NN) ? (g_deg[idx] + 1) : 0;
    __syncthreads();
    for (int d = 512; d > 0; d >>= 1) {
        if (t < d) red[t] += red[t + d];
        __syncthreads();
    }
    if (t == 0) g_bsum[blockIdx.x] = red[0];
}

__global__ void k_top() {
    if (threadIdx.x == 0) {
        int run = 0;
        for (int b = 0; b < NBLK; ++b) {
            int v = g_bsum[b];
            g_bsum[b] = run;
            run += v;
        }
        g_off[NN] = run;
    }
}

__global__ void k_emit() {
    __shared__ int sc[1024];
    int t = threadIdx.x;
    int idx = blockIdx.x * 1024 + t;
    int v = (idx < NN) ? (g_deg[idx] + 1) : 0;
    sc[t] = v;
    __syncthreads();
    for (int d = 1; d < 1024; d <<= 1) {
        int add = (t >= d) ? sc[t - d] : 0;
        __syncthreads();
        sc[t] += add;
        __syncthreads();
    }
    if (idx < NN) {
        int off = g_bsum[blockIdx.x] + sc[t] - v;
        g_off[idx] = off;
        g_srcs[off] = idx;       // self loop in slot 0
        g_cur[idx] = off + 1;
        g_deg[idx] = 0;          // reset for next replay
    }
}

__global__ void k_scatter(const int* __restrict__ ei, int E) {
    int e4 = blockIdx.x * blockDim.x + threadIdx.x;
    if (e4 * 4 < E) {
        int4 sv = ((const int4*)ei)[e4];
        int4 dv = ((const int4*)(ei + E))[e4];
        int ss[4] = {sv.x, sv.y, sv.z, sv.w};
        int dd[4] = {dv.x, dv.y, dv.z, dv.w};
#pragma unroll
        for (int k = 0; k < 4; ++k) {
            int d = dd[k], s = ss[k];
            if (d >= 0 && d < NN && s >= 0 && s < NN) {
                int p = atomicAdd(&g_cur[d], 1);
                if (p >= 0 && p < TOTE) g_srcs[p] = s;
            }
        }
    }
}

// ============================ GEMM (persistent, W-resident, f32x2) ============================
// Grid-stride over 64-row tiles; W (128x128, zero-padded cols) resident in smem.
template <int MODE>
__global__ void __launch_bounds__(256) gemm_kernel(const float4* __restrict__ Aext,
                            const float* __restrict__ W,
                            const float* __restrict__ avs,
                            const float* __restrict__ avd,
                            const float* __restrict__ bias,
                            float* __restrict__ Cext) {
    constexpr int Wn = (MODE == 2) ? DOUT : DH;
    __shared__ ulonglong2 Ws2[128 * 32];     // 64 KB: full W [128 k][128 cols]
    __shared__ float4     As[64 * 32];       // 32 KB A tile

    const float4* A = (MODE == 0) ? Aext : g_t4;

    int tid = threadIdx.x;                   // 256 threads
    int tx = tid & 31, ty = tid >> 5;

    // ---- stage W once per block ----
    if (MODE < 2) {
        const float4* W4 = (const float4*)W;         // [128][128] fp32 = 4096 float4
        for (int i = tid; i < 4096; i += 256)
            cp_async16(((float4*)Ws2) + i, W4 + i);
        cp_async_commit();
    } else {
        float* Wsf = (float*)Ws2;
        for (int i = tid; i < 128 * 128; i += 256) {
            int k = i >> 7, c = i & 127;
            Wsf[i] = (c < Wn) ? W[k * Wn + c] : 0.f;
        }
    }

    // preload epilogue vectors (uniform per thread)
    float as0, as1, as2, as3, ad0, ad1, ad2, ad3;
    if (MODE < 2) {
        as0 = avs[4 * tx + 0]; as1 = avs[4 * tx + 1]; as2 = avs[4 * tx + 2]; as3 = avs[4 * tx + 3];
        ad0 = avd[4 * tx + 0]; ad1 = avd[4 * tx + 1]; ad2 = avd[4 * tx + 2]; ad3 = avd[4 * tx + 3];
    }

    for (int tile = blockIdx.x; tile < NT; tile += GEMM_GRID) {
        int rowBase = tile * 64;
        int rmax = NN - rowBase;

        __syncthreads();                     // protect As from previous tile's readers
        for (int i = tid; i < 64 * 32; i += 256) {
            int r = i >> 5;
            if (r < rmax) cp_async16(&As[i], &A[rowBase * 32 + i]);
            else          As[i] = make_float4(0.f, 0.f, 0.f, 0.f);
        }
        cp_async_commit();
        cp_async_wait_all();                 // A (and, first iter, W) landed
        __syncthreads();

        unsigned long long accL[8], accH[8];
#pragma unroll
        for (int i = 0; i < 8; ++i) { accL[i] = 0ull; accH[i] = 0ull; }

#pragma unroll 2
        for (int k4 = 0; k4 < 32; ++k4) {
            ulonglong2 w0 = Ws2[(k4 * 4 + 0) * 32 + tx];
            ulonglong2 w1 = Ws2[(k4 * 4 + 1) * 32 + tx];
            ulonglong2 w2 = Ws2[(k4 * 4 + 2) * 32 + tx];
            ulonglong2 w3 = Ws2[(k4 * 4 + 3) * 32 + tx];
#pragma unroll
            for (int i = 0; i < 8; ++i) {
                float4 a = As[(ty * 8 + i) * 32 + k4];
                unsigned long long ax = pack2(a.x), ay = pack2(a.y);
                unsigned long long az = pack2(a.z), aw = pack2(a.w);
                fma2(accL[i], ax, w0.x); fma2(accH[i], ax, w0.y);
                fma2(accL[i], ay, w1.x); fma2(accH[i], ay, w1.y);
                fma2(accL[i], az, w2.x); fma2(accH[i], az, w2.y);
                fma2(accL[i], aw, w3.x); fma2(accH[i], aw, w3.y);
            }
        }

        if (MODE < 2) {
#pragma unroll
            for (int i = 0; i < 8; ++i) {
                int row = rowBase + ty * 8 + i;
                float2 lo = unpack2(accL[i]), hi = unpack2(accH[i]);
                float4 acc = make_float4(lo.x, lo.y, hi.x, hi.y);
                float ps = acc.x * as0 + acc.y * as1 + acc.z * as2 + acc.w * as3;
                float pd = acc.x * ad0 + acc.y * ad1 + acc.z * ad2 + acc.w * ad3;
#pragma unroll
                for (int o = 16; o; o >>= 1) {
                    ps += __shfl_xor_sync(0xffffffffu, ps, o);
                    pd += __shfl_xor_sync(0xffffffffu, pd, o);
                }
                if (row < NN) {
                    g_hh[row * 32 + tx] = make_uint2(f2_to_h2(acc.x, acc.y),
                                                     f2_to_h2(acc.z, acc.w));
                    if (tx == 0) { g_as[row] = ps; g_ad[row] = pd; }
                }
            }
        } else {
#pragma unroll
            for (int i = 0; i < 8; ++i) {
                int row = rowBase + ty * 8 + i;
                if (row < NN) {
                    float2 lo = unpack2(accL[i]), hi = unpack2(accH[i]);
                    float v[4] = {lo.x, lo.y, hi.x, hi.y};
#pragma unroll
                    for (int j = 0; j < 4; ++j) {
                        int col = 4 * tx + j;
                        if (col < DOUT) Cext[row * DOUT + col] = v[j] + bias[col];
                    }
                }
            }
        }
    }
}

// ==================== segment softmax + aggregation (2-way; optional relu-out) ====================
template <bool RELU_OUT>
__global__ void __launch_bounds__(256) agg_kernel(const float* __restrict__ bias) {
    int w = (blockIdx.x * blockDim.x + threadIdx.x) >> 5;
    if (w >= NN) return;
    int lane = threadIdx.x & 31;
    int beg = g_off[w], end = g_off[w + 1];
    float adn = g_ad[w];

    float4 acc0 = make_float4(0.f, 0.f, 0.f, 0.f);
    float4 acc1 = make_float4(0.f, 0.f, 0.f, 0.f);
    float den = 0.f;

    for (int b = beg; b < end; b += 32) {
        int j = b + lane;
        int s = 0; float ex = 0.f;
        if (j < end) {
            s = g_srcs[j];
            float e = g_as[s] + adn;
            e = (e > 0.f) ? e : 0.2f * e;
            ex = __expf(e);
        }
        den += ex;
        int cnt = min(32, end - b);
        int jj = 0;
        for (; jj + 2 <= cnt; jj += 2) {
            int   s0 = __shfl_sync(0xffffffffu, s,  jj);
            int   s1 = __shfl_sync(0xffffffffu, s,  jj + 1);
            float w0 = __shfl_sync(0xffffffffu, ex, jj);
            float w1 = __shfl_sync(0xffffffffu, ex, jj + 1);
            uint2 u0 = g_hh[s0 * 32 + lane];
            uint2 u1 = g_hh[s1 * 32 + lane];
            float2 f0a = h2_to_f2(u0.x), f0b = h2_to_f2(u0.y);
            float2 f1a = h2_to_f2(u1.x), f1b = h2_to_f2(u1.y);
            acc0.x += w0 * f0a.x; acc0.y += w0 * f0a.y; acc0.z += w0 * f0b.x; acc0.w += w0 * f0b.y;
            acc1.x += w1 * f1a.x; acc1.y += w1 * f1a.y; acc1.z += w1 * f1b.x; acc1.w += w1 * f1b.y;
        }
        if (jj < cnt) {
            int   s0 = __shfl_sync(0xffffffffu, s,  jj);
            float w0 = __shfl_sync(0xffffffffu, ex, jj);
            uint2 u0 = g_hh[s0 * 32 + lane];
            float2 f0a = h2_to_f2(u0.x), f0b = h2_to_f2(u0.y);
            acc0.x += w0 * f0a.x; acc0.y += w0 * f0a.y; acc0.z += w0 * f0b.x; acc0.w += w0 * f0b.y;
        }
    }
#pragma unroll
    for (int o = 16; o; o >>= 1) den += __shfl_xor_sync(0xffffffffu, den, o);
    float inv = 1.0f / den;

    float b0 = bias[4 * lane + 0], b1 = bias[4 * lane + 1];
    float b2 = bias[4 * lane + 2], b3 = bias[4 * lane + 3];
    float4 v = make_float4((acc0.x + acc1.x) * inv + b0,
                           (acc0.y + acc1.y) * inv + b1,
                           (acc0.z + acc1.z) * inv + b2,
                           (acc0.w + acc1.w) * inv + b3);
    if (RELU_OUT) {
        v.x = fmaxf(v.x, 0.f); v.y = fmaxf(v.y, 0.f);
        v.z = fmaxf(v.z, 0.f); v.w = fmaxf(v.w, 0.f);
    }
    g_t4[w * 32 + lane] = v;
}

// ============================ launch ============================
extern "C" void kernel_launch(void* const* d_in, const int* in_sizes, int n_in,
                              void* d_out, int out_size) {
    const float* x   = (const float*)d_in[0];
    const int*   ei  = (const int*)d_in[1];     // int32 (JAX x64-disabled)
    const float* W1  = (const float*)d_in[2];
    const float* a1s = (const float*)d_in[3];
    const float* a1d = (const float*)d_in[4];
    const float* b1  = (const float*)d_in[5];
    const float* W2  = (const float*)d_in[6];
    const float* a2s = (const float*)d_in[7];
    const float* a2d = (const float*)d_in[8];
    const float* b2  = (const float*)d_in[9];
    const float* fcw = (const float*)d_in[10];
    const float* fcb = (const float*)d_in[11];
    float*       out = (float*)d_out;
    int E = in_sizes[1] / 2;
    int E4 = (E + 3) / 4;

    int agg_blocks = (NN * 32 + 255) / 256;

    // CSR build (parallel scan)
    k_count<<<(E4 + 255) / 256, 256>>>(ei, E);
    k_blocksum<<<NBLK, 1024>>>();
    k_top<<<1, 32>>>();
    k_emit<<<NBLK, 1024>>>();
    k_scatter<<<(E4 + 255) / 256, 256>>>(ei, E);

    // layer 1
    gemm_kernel<0><<<GEMM_GRID, 256>>>((const float4*)x, W1, a1s, a1d, nullptr, nullptr);
    agg_kernel<true><<<agg_blocks, 256>>>(b1);   // relu fused into output
    // layer 2 (input already relu'd)
    gemm_kernel<1><<<GEMM_GRID, 256>>>(nullptr, W2, a2s, a2d, nullptr, nullptr);
    agg_kernel<false><<<agg_blocks, 256>>>(b2);
    // output head
    gemm_kernel<2><<<GEMM_GRID, 256>>>(nullptr, fcw, nullptr, nullptr, fcb, out);
}

// round 16
// speedup vs baseline: 1.0737x; 1.0737x over previous
#include <cuda_runtime.h>
#include <cuda_fp16.h>
#include <math.h>

#define NN   50000
#define DH   128
#define DOUT 57
#define TOTE (800000 + NN)
#define NBLK 49   // ceil(50000/1024)

// -------- scratch (__device__ globals; zero-initialized at load) --------
__device__ uint2  g_hh[NN * 32];   // h in fp16: [N][32] x (2 half2)
__device__ float4 g_t4[NN * 32];   // aggregation output [N,128] fp32
__device__ float  g_as[NN];        // alpha_src per node
__device__ float  g_ad[NN];        // alpha_dst per node
__device__ int    g_deg[NN];       // zero-init; reset to 0 by k_emit each replay
__device__ int    g_off[NN + 1];
__device__ int    g_cur[NN];
__device__ int    g_srcs[TOTE];    // CSR (by dst): src node per edge
__device__ int    g_bsum[NBLK];    // per-block (deg+1) sums

// ---------------- f32x2 packed-FMA helpers (sm_103a) ----------------
__device__ __forceinline__ unsigned long long pack2(float v) {
    unsigned long long r;
    asm("mov.b64 %0, {%1, %1};" : "=l"(r) : "f"(v));
    return r;
}
__device__ __forceinline__ void fma2(unsigned long long& d,
                                     unsigned long long a, unsigned long long b) {
    asm("fma.rn.f32x2 %0, %1, %2, %0;" : "+l"(d) : "l"(a), "l"(b));
}
__device__ __forceinline__ float2 unpack2(unsigned long long v) {
    float x, y;
    asm("mov.b64 {%0, %1}, %2;" : "=f"(x), "=f"(y) : "l"(v));
    return make_float2(x, y);
}

// ---------------- fp16x2 <-> fp32 helpers ----------------
__device__ __forceinline__ unsigned int f2_to_h2(float lo, float hi) {
    unsigned int r;
    asm("cvt.rn.f16x2.f32 %0, %2, %1;" : "=r"(r) : "f"(lo), "f"(hi));
    return r;
}
__device__ __forceinline__ float2 h2_to_f2(unsigned int u) {
    __half2 h = *reinterpret_cast<__half2*>(&u);
    return __half22float2(h);
}

// ---------------- cp.async helpers ----------------
__device__ __forceinline__ void cp_async16(void* smem_dst, const void* gmem_src) {
    unsigned int d = (unsigned int)__cvta_generic_to_shared(smem_dst);
    asm volatile("cp.async.cg.shared.global [%0], [%1], 16;" :: "r"(d), "l"(gmem_src));
}
__device__ __forceinline__ void cp_async_commit() {
    asm volatile("cp.async.commit_group;" ::: "memory");
}
__device__ __forceinline__ void cp_async_wait_all() {
    asm volatile("cp.async.wait_group 0;" ::: "memory");
}

// ============================ CSR build (5 small kernels) ============================
__global__ void k_count(const int* __restrict__ ei, int E) {
    int e4 = blockIdx.x * blockDim.x + threadIdx.x;
    if (e4 * 4 < E) {
        int4 d = ((const int4*)(ei + E))[e4];
        if (d.x >= 0 && d.x < NN) atomicAdd(&g_deg[d.x], 1);
        if (d.y >= 0 && d.y < NN) atomicAdd(&g_deg[d.y], 1);
        if (d.z >= 0 && d.z < NN) atomicAdd(&g_deg[d.z], 1);
        if (d.w >= 0 && d.w < NN) atomicAdd(&g_deg[d.w], 1);
    }
}

__global__ void k_blocksum() {
    __shared__ int red[1024];
    int t = threadIdx.x;
    int idx = blockIdx.x * 1024 + t;
    red[t] = (idx < NN) ? (g_deg[idx] + 1) : 0;
    __syncthreads();
    for (int d = 512; d > 0; d >>= 1) {
        if (t < d) red[t] += red[t + d];
        __syncthreads();
    }
    if (t == 0) g_bsum[blockIdx.x] = red[0];
}

__global__ void k_top() {
    if (threadIdx.x == 0) {
        int run = 0;
        for (int b = 0; b < NBLK; ++b) {
            int v = g_bsum[b];
            g_bsum[b] = run;
            run += v;
        }
        g_off[NN] = run;
    }
}

__global__ void k_emit() {
    __shared__ int sc[1024];
    int t = threadIdx.x;
    int idx = blockIdx.x * 1024 + t;
    int v = (idx < NN) ? (g_deg[idx] + 1) : 0;
    sc[t] = v;
    __syncthreads();
    for (int d = 1; d < 1024; d <<= 1) {
        int add = (t >= d) ? sc[t - d] : 0;
        __syncthreads();
        sc[t] += add;
        __syncthreads();
    }
    if (idx < NN) {
        int off = g_bsum[blockIdx.x] + sc[t] - v;
        g_off[idx] = off;
        g_srcs[off] = idx;       // self loop in slot 0
        g_cur[idx] = off + 1;
        g_deg[idx] = 0;          // reset for next replay
    }
}

__global__ void k_scatter(const int* __restrict__ ei, int E) {
    int e4 = blockIdx.x * blockDim.x + threadIdx.x;
    if (e4 * 4 < E) {
        int4 sv = ((const int4*)ei)[e4];
        int4 dv = ((const int4*)(ei + E))[e4];
        int ss[4] = {sv.x, sv.y, sv.z, sv.w};
        int dd[4] = {dv.x, dv.y, dv.z, dv.w};
#pragma unroll
        for (int k = 0; k < 4; ++k) {
            int d = dd[k], s = ss[k];
            if (d >= 0 && d < NN && s >= 0 && s < NN) {
                int p = atomicAdd(&g_cur[d], 1);
                if (p >= 0 && p < TOTE) g_srcs[p] = s;
            }
        }
    }
}

// ============================ GEMM (R14: cp.async double-buffered, f32x2) ============================
template <int MODE>
__global__ void __launch_bounds__(256) gemm_kernel(const float4* __restrict__ Aext,
                            const float* __restrict__ W,
                            const float* __restrict__ avs,
                            const float* __restrict__ avd,
                            const float* __restrict__ bias,
                            float* __restrict__ Cext) {
    constexpr int Wn = (MODE == 2) ? DOUT : DH;
    __shared__ float4     As[64 * 32];       // 32 KB A tile
    __shared__ ulonglong2 Ws2[2][32 * 32];   // 2 x 16 KB W quarters

    const float4* A = (MODE == 0) ? Aext : g_t4;

    int tid = threadIdx.x;                   // 256 threads
    int tx = tid & 31, ty = tid >> 5;
    int rowBase = blockIdx.x * 64;
    int rmax = NN - rowBase;

    for (int i = tid; i < 64 * 32; i += 256) {
        int r = i >> 5;
        if (r < rmax) cp_async16(&As[i], &A[rowBase * 32 + i]);
        else          As[i] = make_float4(0.f, 0.f, 0.f, 0.f);
    }
    if (MODE < 2) {
        const float4* W4 = (const float4*)W;
        for (int i = tid; i < 1024; i += 256)
            cp_async16(((float4*)Ws2[0]) + i, W4 + i);
    }
    cp_async_commit();

    unsigned long long accL[8], accH[8];
#pragma unroll
    for (int i = 0; i < 8; ++i) { accL[i] = 0ull; accH[i] = 0ull; }

    for (int q = 0; q < 4; ++q) {
        const ulonglong2* Wb;
        if (MODE < 2) {
            cp_async_wait_all();
            __syncthreads();
            if (q < 3) {
                const float4* W4 = (const float4*)W;
                for (int i = tid; i < 1024; i += 256)
                    cp_async16(((float4*)Ws2[(q + 1) & 1]) + i, W4 + (q + 1) * 1024 + i);
                cp_async_commit();
            }
            Wb = Ws2[q & 1];
        } else {
            __syncthreads();
            float* Wsf = (float*)Ws2[0];
            for (int i = tid; i < 32 * DH; i += 256) {
                int k = i >> 7, c = i & 127;
                Wsf[i] = (c < Wn) ? W[(q * 32 + k) * Wn + c] : 0.f;
            }
            if (q == 0) cp_async_wait_all();
            __syncthreads();
            Wb = Ws2[0];
        }

#pragma unroll 2
        for (int k4 = 0; k4 < 8; ++k4) {
            ulonglong2 w0 = Wb[(k4 * 4 + 0) * 32 + tx];
            ulonglong2 w1 = Wb[(k4 * 4 + 1) * 32 + tx];
            ulonglong2 w2 = Wb[(k4 * 4 + 2) * 32 + tx];
            ulonglong2 w3 = Wb[(k4 * 4 + 3) * 32 + tx];
#pragma unroll
            for (int i = 0; i < 8; ++i) {
                float4 a = As[(ty * 8 + i) * 32 + q * 8 + k4];
                unsigned long long ax = pack2(a.x), ay = pack2(a.y);
                unsigned long long az = pack2(a.z), aw = pack2(a.w);
                fma2(accL[i], ax, w0.x); fma2(accH[i], ax, w0.y);
                fma2(accL[i], ay, w1.x); fma2(accH[i], ay, w1.y);
                fma2(accL[i], az, w2.x); fma2(accH[i], az, w2.y);
                fma2(accL[i], aw, w3.x); fma2(accH[i], aw, w3.y);
            }
        }
    }

    if (MODE < 2) {
        float as0 = avs[4 * tx + 0], as1 = avs[4 * tx + 1], as2 = avs[4 * tx + 2], as3 = avs[4 * tx + 3];
        float ad0 = avd[4 * tx + 0], ad1 = avd[4 * tx + 1], ad2 = avd[4 * tx + 2], ad3 = avd[4 * tx + 3];
#pragma unroll
        for (int i = 0; i < 8; ++i) {
            int row = rowBase + ty * 8 + i;
            float2 lo = unpack2(accL[i]), hi = unpack2(accH[i]);
            float4 acc = make_float4(lo.x, lo.y, hi.x, hi.y);
            float ps = acc.x * as0 + acc.y * as1 + acc.z * as2 + acc.w * as3;
            float pd = acc.x * ad0 + acc.y * ad1 + acc.z * ad2 + acc.w * ad3;
#pragma unroll
            for (int o = 16; o; o >>= 1) {
                ps += __shfl_xor_sync(0xffffffffu, ps, o);
                pd += __shfl_xor_sync(0xffffffffu, pd, o);
            }
            if (row < NN) {
                g_hh[row * 32 + tx] = make_uint2(f2_to_h2(acc.x, acc.y),
                                                 f2_to_h2(acc.z, acc.w));
                if (tx == 0) { g_as[row] = ps; g_ad[row] = pd; }
            }
        }
    } else {
#pragma unroll
        for (int i = 0; i < 8; ++i) {
            int row = rowBase + ty * 8 + i;
            if (row < NN) {
                float2 lo = unpack2(accL[i]), hi = unpack2(accH[i]);
                float v[4] = {lo.x, lo.y, hi.x, hi.y};
#pragma unroll
                for (int j = 0; j < 4; ++j) {
                    int col = 4 * tx + j;
                    if (col < DOUT) Cext[row * DOUT + col] = v[j] + bias[col];
                }
            }
        }
    }
}

// ==================== segment softmax + aggregation (2-way; optional relu-out) ====================
template <bool RELU_OUT>
__global__ void __launch_bounds__(256) agg_kernel(const float* __restrict__ bias) {
    int w = (blockIdx.x * blockDim.x + threadIdx.x) >> 5;
    if (w >= NN) return;
    int lane = threadIdx.x & 31;
    int beg = g_off[w], end = g_off[w + 1];
    float adn = g_ad[w];

    float4 acc0 = make_float4(0.f, 0.f, 0.f, 0.f);
    float4 acc1 = make_float4(0.f, 0.f, 0.f, 0.f);
    float den = 0.f;

    for (int b = beg; b < end; b += 32) {
        int j = b + lane;
        int s = 0; float ex = 0.f;
        if (j < end) {
            s = g_srcs[j];
            float e = g_as[s] + adn;
            e = (e > 0.f) ? e : 0.2f * e;
            ex = __expf(e);
        }
        den += ex;
        int cnt = min(32, end - b);
        int jj = 0;
        for (; jj + 2 <= cnt; jj += 2) {
            int   s0 = __shfl_sync(0xffffffffu, s,  jj);
            int   s1 = __shfl_sync(0xffffffffu, s,  jj + 1);
            float w0 = __shfl_sync(0xffffffffu, ex, jj);
            float w1 = __shfl_sync(0xffffffffu, ex, jj + 1);
            uint2 u0 = g_hh[s0 * 32 + lane];
            uint2 u1 = g_hh[s1 * 32 + lane];
            float2 f0a = h2_to_f2(u0.x), f0b = h2_to_f2(u0.y);
            float2 f1a = h2_to_f2(u1.x), f1b = h2_to_f2(u1.y);
            acc0.x += w0 * f0a.x; acc0.y += w0 * f0a.y; acc0.z += w0 * f0b.x; acc0.w += w0 * f0b.y;
            acc1.x += w1 * f1a.x; acc1.y += w1 * f1a.y; acc1.z += w1 * f1b.x; acc1.w += w1 * f1b.y;
        }
        if (jj < cnt) {
            int   s0 = __shfl_sync(0xffffffffu, s,  jj);
            float w0 = __shfl_sync(0xffffffffu, ex, jj);
            uint2 u0 = g_hh[s0 * 32 + lane];
            float2 f0a = h2_to_f2(u0.x), f0b = h2_to_f2(u0.y);
            acc0.x += w0 * f0a.x; acc0.y += w0 * f0a.y; acc0.z += w0 * f0b.x; acc0.w += w0 * f0b.y;
        }
    }
#pragma unroll
    for (int o = 16; o; o >>= 1) den += __shfl_xor_sync(0xffffffffu, den, o);
    float inv = 1.0f / den;

    float b0 = bias[4 * lane + 0], b1 = bias[4 * lane + 1];
    float b2 = bias[4 * lane + 2], b3 = bias[4 * lane + 3];
    float4 v = make_float4((acc0.x + acc1.x) * inv + b0,
                           (acc0.y + acc1.y) * inv + b1,
                           (acc0.z + acc1.z) * inv + b2,
                           (acc0.w + acc1.w) * inv + b3);
    if (RELU_OUT) {
        v.x = fmaxf(v.x, 0.f); v.y = fmaxf(v.y, 0.f);
        v.z = fmaxf(v.z, 0.f); v.w = fmaxf(v.w, 0.f);
    }
    g_t4[w * 32 + lane] = v;
}

// ============================ launch (2-stream fork/join) ============================
extern "C" void kernel_launch(void* const* d_in, const int* in_sizes, int n_in,
                              void* d_out, int out_size) {
    const float* x   = (const float*)d_in[0];
    const int*   ei  = (const int*)d_in[1];     // int32 (JAX x64-disabled)
    const float* W1  = (const float*)d_in[2];
    const float* a1s = (const float*)d_in[3];
    const float* a1d = (const float*)d_in[4];
    const float* b1  = (const float*)d_in[5];
    const float* W2  = (const float*)d_in[6];
    const float* a2s = (const float*)d_in[7];
    const float* a2d = (const float*)d_in[8];
    const float* b2  = (const float*)d_in[9];
    const float* fcw = (const float*)d_in[10];
    const float* fcb = (const float*)d_in[11];
    float*       out = (float*)d_out;
    int E = in_sizes[1] / 2;
    int E4 = (E + 3) / 4;

    int gemm_blocks = (NN + 63) / 64;
    int agg_blocks  = (NN * 32 + 255) / 256;

    // side stream + events for the CSR chain (host-side handles only; no device mem).
    // Not destroyed: kernel_launch is invoked only a handful of times (graph replays
    // do not re-enter this function), so the few leaked handles are harmless.
    cudaStream_t s2;
    cudaStreamCreateWithFlags(&s2, cudaStreamNonBlocking);
    cudaEvent_t evFork, evJoin;
    cudaEventCreateWithFlags(&evFork, cudaEventDisableTiming);
    cudaEventCreateWithFlags(&evJoin, cudaEventDisableTiming);

    // fork: CSR chain runs on s2 concurrently with gemm0 on the main stream
    cudaEventRecord(evFork, 0);
    cudaStreamWaitEvent(s2, evFork, 0);

    k_count<<<(E4 + 255) / 256, 256, 0, s2>>>(ei, E);
    k_blocksum<<<NBLK, 1024, 0, s2>>>();
    k_top<<<1, 32, 0, s2>>>();
    k_emit<<<NBLK, 1024, 0, s2>>>();
    k_scatter<<<(E4 + 255) / 256, 256, 0, s2>>>(ei, E);
    cudaEventRecord(evJoin, s2);

    // main stream: layer-1 GEMM (independent of CSR)
    gemm_kernel<0><<<gemm_blocks, 256>>>((const float4*)x, W1, a1s, a1d, nullptr, nullptr);

    // join: agg1 needs both CSR and gemm0
    cudaStreamWaitEvent(0, evJoin, 0);
    agg_kernel<true><<<agg_blocks, 256>>>(b1);   // relu fused into output
    // layer 2 (input already relu'd)
    gemm_kernel<1><<<gemm_blocks, 256>>>(nullptr, W2, a2s, a2d, nullptr, nullptr);
    agg_kernel<false><<<agg_blocks, 256>>>(b2);
    // output head
    gemm_kernel<2><<<gemm_blocks, 256>>>(nullptr, fcw, nullptr, nullptr, fcb, out);
}

// round 17
// speedup vs baseline: 1.1793x; 1.0984x over previous
#include <cuda_runtime.h>
#include <cuda_fp16.h>
#include <math.h>

#define NN   50000
#define DH   128
#define DOUT 57
#define TOTE (800000 + NN)
#define NBLK 49   // ceil(50000/1024)

// -------- scratch (__device__ globals; zero-initialized at load) --------
__device__ uint2  g_hh[NN * 32];   // h in fp16: [N][32] x (2 half2)
__device__ float4 g_t4[NN * 32];   // aggregation output [N,128] fp32
__device__ float  g_as[NN];        // alpha_src per node
__device__ float  g_ad[NN];        // alpha_dst per node
__device__ int    g_deg[NN];       // zero-init; reset to 0 by k_emit each replay
__device__ int    g_off[NN + 1];
__device__ int    g_cur[NN];
__device__ int    g_srcs[TOTE];    // CSR (by dst): src node per edge
__device__ int    g_bsum[NBLK];    // per-block (deg+1) sums

// ---------------- f32x2 packed-FMA helpers (sm_103a) ----------------
__device__ __forceinline__ unsigned long long pack2(float v) {
    unsigned long long r;
    asm("mov.b64 %0, {%1, %1};" : "=l"(r) : "f"(v));
    return r;
}
__device__ __forceinline__ void fma2(unsigned long long& d,
                                     unsigned long long a, unsigned long long b) {
    asm("fma.rn.f32x2 %0, %1, %2, %0;" : "+l"(d) : "l"(a), "l"(b));
}
__device__ __forceinline__ float2 unpack2(unsigned long long v) {
    float x, y;
    asm("mov.b64 {%0, %1}, %2;" : "=f"(x), "=f"(y) : "l"(v));
    return make_float2(x, y);
}

// ---------------- fp16x2 <-> fp32 helpers ----------------
__device__ __forceinline__ unsigned int f2_to_h2(float lo, float hi) {
    unsigned int r;
    asm("cvt.rn.f16x2.f32 %0, %2, %1;" : "=r"(r) : "f"(lo), "f"(hi));
    return r;
}
__device__ __forceinline__ float2 h2_to_f2(unsigned int u) {
    __half2 h = *reinterpret_cast<__half2*>(&u);
    return __half22float2(h);
}

// ---------------- cp.async helpers ----------------
__device__ __forceinline__ void cp_async16(void* smem_dst, const void* gmem_src) {
    unsigned int d = (unsigned int)__cvta_generic_to_shared(smem_dst);
    asm volatile("cp.async.cg.shared.global [%0], [%1], 16;" :: "r"(d), "l"(gmem_src));
}
__device__ __forceinline__ void cp_async_commit() {
    asm volatile("cp.async.commit_group;" ::: "memory");
}
__device__ __forceinline__ void cp_async_wait_all() {
    asm volatile("cp.async.wait_group 0;" ::: "memory");
}

// ============================ CSR build (5 small kernels) ============================
__global__ void k_count(const int* __restrict__ ei, int E) {
    int e4 = blockIdx.x * blockDim.x + threadIdx.x;
    if (e4 * 4 < E) {
        int4 d = ((const int4*)(ei + E))[e4];
        if (d.x >= 0 && d.x < NN) atomicAdd(&g_deg[d.x], 1);
        if (d.y >= 0 && d.y < NN) atomicAdd(&g_deg[d.y], 1);
        if (d.z >= 0 && d.z < NN) atomicAdd(&g_deg[d.z], 1);
        if (d.w >= 0 && d.w < NN) atomicAdd(&g_deg[d.w], 1);
    }
}

__global__ void k_blocksum() {
    __shared__ int red[1024];
    int t = threadIdx.x;
    int idx = blockIdx.x * 1024 + t;
    red[t] = (idx < NN) ? (g_deg[idx] + 1) : 0;
    __syncthreads();
    for (int d = 512; d > 0; d >>= 1) {
        if (t < d) red[t] += red[t + d];
        __syncthreads();
    }
    if (t == 0) g_bsum[blockIdx.x] = red[0];
}

__global__ void k_top() {
    if (threadIdx.x == 0) {
        int run = 0;
        for (int b = 0; b < NBLK; ++b) {
            int v = g_bsum[b];
            g_bsum[b] = run;
            run += v;
        }
        g_off[NN] = run;
    }
}

__global__ void k_emit() {
    __shared__ int sc[1024];
    int t = threadIdx.x;
    int idx = blockIdx.x * 1024 + t;
    int v = (idx < NN) ? (g_deg[idx] + 1) : 0;
    sc[t] = v;
    __syncthreads();
    for (int d = 1; d < 1024; d <<= 1) {
        int add = (t >= d) ? sc[t - d] : 0;
        __syncthreads();
        sc[t] += add;
        __syncthreads();
    }
    if (idx < NN) {
        int off = g_bsum[blockIdx.x] + sc[t] - v;
        g_off[idx] = off;
        g_srcs[off] = idx;       // self loop in slot 0
        g_cur[idx] = off + 1;
        g_deg[idx] = 0;          // reset for next replay
    }
}

__global__ void k_scatter(const int* __restrict__ ei, int E) {
    int e4 = blockIdx.x * blockDim.x + threadIdx.x;
    if (e4 * 4 < E) {
        int4 sv = ((const int4*)ei)[e4];
        int4 dv = ((const int4*)(ei + E))[e4];
        int ss[4] = {sv.x, sv.y, sv.z, sv.w};
        int dd[4] = {dv.x, dv.y, dv.z, dv.w};
#pragma unroll
        for (int k = 0; k < 4; ++k) {
            int d = dd[k], s = ss[k];
            if (d >= 0 && d < NN && s >= 0 && s < NN) {
                int p = atomicAdd(&g_cur[d], 1);
                if (p >= 0 && p < TOTE) g_srcs[p] = s;
            }
        }
    }
}

// ============================ GEMM (128-col: cp.async double-buffered, f32x2) ============================
// MODE 0: A=ext(x), h->g_hh(fp16), fused alpha.  MODE 1: A=g_t4 (already relu'd), same.
template <int MODE>
__global__ void __launch_bounds__(256) gemm_kernel(const float4* __restrict__ Aext,
                            const float* __restrict__ W,
                            const float* __restrict__ avs,
                            const float* __restrict__ avd) {
    __shared__ float4     As[64 * 32];       // 32 KB A tile
    __shared__ ulonglong2 Ws2[2][32 * 32];   // 2 x 16 KB W quarters

    const float4* A = (MODE == 0) ? Aext : g_t4;

    int tid = threadIdx.x;                   // 256 threads
    int tx = tid & 31, ty = tid >> 5;
    int rowBase = blockIdx.x * 64;
    int rmax = NN - rowBase;

    for (int i = tid; i < 64 * 32; i += 256) {
        int r = i >> 5;
        if (r < rmax) cp_async16(&As[i], &A[rowBase * 32 + i]);
        else          As[i] = make_float4(0.f, 0.f, 0.f, 0.f);
    }
    {
        const float4* W4 = (const float4*)W;
        for (int i = tid; i < 1024; i += 256)
            cp_async16(((float4*)Ws2[0]) + i, W4 + i);
    }
    cp_async_commit();

    unsigned long long accL[8], accH[8];
#pragma unroll
    for (int i = 0; i < 8; ++i) { accL[i] = 0ull; accH[i] = 0ull; }

    for (int q = 0; q < 4; ++q) {
        cp_async_wait_all();
        __syncthreads();
        if (q < 3) {
            const float4* W4 = (const float4*)W;
            for (int i = tid; i < 1024; i += 256)
                cp_async16(((float4*)Ws2[(q + 1) & 1]) + i, W4 + (q + 1) * 1024 + i);
            cp_async_commit();
        }
        const ulonglong2* Wb = Ws2[q & 1];

#pragma unroll 2
        for (int k4 = 0; k4 < 8; ++k4) {
            ulonglong2 w0 = Wb[(k4 * 4 + 0) * 32 + tx];
            ulonglong2 w1 = Wb[(k4 * 4 + 1) * 32 + tx];
            ulonglong2 w2 = Wb[(k4 * 4 + 2) * 32 + tx];
            ulonglong2 w3 = Wb[(k4 * 4 + 3) * 32 + tx];
#pragma unroll
            for (int i = 0; i < 8; ++i) {
                float4 a = As[(ty * 8 + i) * 32 + q * 8 + k4];
                unsigned long long ax = pack2(a.x), ay = pack2(a.y);
                unsigned long long az = pack2(a.z), aw = pack2(a.w);
                fma2(accL[i], ax, w0.x); fma2(accH[i], ax, w0.y);
                fma2(accL[i], ay, w1.x); fma2(accH[i], ay, w1.y);
                fma2(accL[i], az, w2.x); fma2(accH[i], az, w2.y);
                fma2(accL[i], aw, w3.x); fma2(accH[i], aw, w3.y);
            }
        }
    }

    float as0 = avs[4 * tx + 0], as1 = avs[4 * tx + 1], as2 = avs[4 * tx + 2], as3 = avs[4 * tx + 3];
    float ad0 = avd[4 * tx + 0], ad1 = avd[4 * tx + 1], ad2 = avd[4 * tx + 2], ad3 = avd[4 * tx + 3];
#pragma unroll
    for (int i = 0; i < 8; ++i) {
        int row = rowBase + ty * 8 + i;
        float2 lo = unpack2(accL[i]), hi = unpack2(accH[i]);
        float4 acc = make_float4(lo.x, lo.y, hi.x, hi.y);
        float ps = acc.x * as0 + acc.y * as1 + acc.z * as2 + acc.w * as3;
        float pd = acc.x * ad0 + acc.y * ad1 + acc.z * ad2 + acc.w * ad3;
#pragma unroll
        for (int o = 16; o; o >>= 1) {
            ps += __shfl_xor_sync(0xffffffffu, ps, o);
            pd += __shfl_xor_sync(0xffffffffu, pd, o);
        }
        if (row < NN) {
            g_hh[row * 32 + tx] = make_uint2(f2_to_h2(acc.x, acc.y),
                                             f2_to_h2(acc.z, acc.w));
            if (tx == 0) { g_as[row] = ps; g_ad[row] = pd; }
        }
    }
}

// ============================ output GEMM (64-col tile, W resident) ============================
// C[N,57] = g_t4 @ fcw + fcb. Thread owns 2 cols (64-col tile, pad 57->64): half the FMAs.
__global__ void __launch_bounds__(256) gemm_out(const float* __restrict__ W,
                                                const float* __restrict__ bias,
                                                float* __restrict__ Cext) {
    __shared__ float4             As[64 * 32];    // 32 KB A tile
    __shared__ unsigned long long Wp[128 * 32];   // 32 KB: [128 k][32 col-pairs]

    int tid = threadIdx.x;
    int tx = tid & 31, ty = tid >> 5;
    int rowBase = blockIdx.x * 64;
    int rmax = NN - rowBase;

    // A tile async
    for (int i = tid; i < 64 * 32; i += 256) {
        int r = i >> 5;
        if (r < rmax) cp_async16(&As[i], &g_t4[rowBase * 32 + i]);
        else          As[i] = make_float4(0.f, 0.f, 0.f, 0.f);
    }
    cp_async_commit();

    // W staged once, zero-padded to 64 cols (rows of 57 floats: sync scalar stage)
    float* Wsf = (float*)Wp;
    for (int i = tid; i < 128 * 64; i += 256) {
        int k = i >> 6, c = i & 63;
        Wsf[i] = (c < DOUT) ? W[k * DOUT + c] : 0.f;
    }
    cp_async_wait_all();
    __syncthreads();

    unsigned long long acc[8];
#pragma unroll
    for (int i = 0; i < 8; ++i) acc[i] = 0ull;

#pragma unroll 2
    for (int k4 = 0; k4 < 32; ++k4) {
        unsigned long long w0 = Wp[(k4 * 4 + 0) * 32 + tx];
        unsigned long long w1 = Wp[(k4 * 4 + 1) * 32 + tx];
        unsigned long long w2 = Wp[(k4 * 4 + 2) * 32 + tx];
        unsigned long long w3 = Wp[(k4 * 4 + 3) * 32 + tx];
#pragma unroll
        for (int i = 0; i < 8; ++i) {
            float4 a = As[(ty * 8 + i) * 32 + k4];
            fma2(acc[i], pack2(a.x), w0);
            fma2(acc[i], pack2(a.y), w1);
            fma2(acc[i], pack2(a.z), w2);
            fma2(acc[i], pack2(a.w), w3);
        }
    }

    int c0 = 2 * tx, c1 = 2 * tx + 1;
    float b0v = (c0 < DOUT) ? bias[c0] : 0.f;
    float b1v = (c1 < DOUT) ? bias[c1] : 0.f;
#pragma unroll
    for (int i = 0; i < 8; ++i) {
        int row = rowBase + ty * 8 + i;
        if (row < NN) {
            float2 v = unpack2(acc[i]);
            if (c0 < DOUT) Cext[row * DOUT + c0] = v.x + b0v;
            if (c1 < DOUT) Cext[row * DOUT + c1] = v.y + b1v;
        }
    }
}

// ==================== segment softmax + aggregation (2-way; optional relu-out) ====================
template <bool RELU_OUT>
__global__ void __launch_bounds__(256) agg_kernel(const float* __restrict__ bias) {
    int w = (blockIdx.x * blockDim.x + threadIdx.x) >> 5;
    if (w >= NN) return;
    int lane = threadIdx.x & 31;
    int beg = g_off[w], end = g_off[w + 1];
    float adn = g_ad[w];

    float4 acc0 = make_float4(0.f, 0.f, 0.f, 0.f);
    float4 acc1 = make_float4(0.f, 0.f, 0.f, 0.f);
    float den = 0.f;

    for (int b = beg; b < end; b += 32) {
        int j = b + lane;
        int s = 0; float ex = 0.f;
        if (j < end) {
            s = g_srcs[j];
            float e = g_as[s] + adn;
            e = (e > 0.f) ? e : 0.2f * e;
            ex = __expf(e);
        }
        den += ex;
        int cnt = min(32, end - b);
        int jj = 0;
        for (; jj + 2 <= cnt; jj += 2) {
            int   s0 = __shfl_sync(0xffffffffu, s,  jj);
            int   s1 = __shfl_sync(0xffffffffu, s,  jj + 1);
            float w0 = __shfl_sync(0xffffffffu, ex, jj);
            float w1 = __shfl_sync(0xffffffffu, ex, jj + 1);
            uint2 u0 = g_hh[s0 * 32 + lane];
            uint2 u1 = g_hh[s1 * 32 + lane];
            float2 f0a = h2_to_f2(u0.x), f0b = h2_to_f2(u0.y);
            float2 f1a = h2_to_f2(u1.x), f1b = h2_to_f2(u1.y);
            acc0.x += w0 * f0a.x; acc0.y += w0 * f0a.y; acc0.z += w0 * f0b.x; acc0.w += w0 * f0b.y;
            acc1.x += w1 * f1a.x; acc1.y += w1 * f1a.y; acc1.z += w1 * f1b.x; acc1.w += w1 * f1b.y;
        }
        if (jj < cnt) {
            int   s0 = __shfl_sync(0xffffffffu, s,  jj);
            float w0 = __shfl_sync(0xffffffffu, ex, jj);
            uint2 u0 = g_hh[s0 * 32 + lane];
            float2 f0a = h2_to_f2(u0.x), f0b = h2_to_f2(u0.y);
            acc0.x += w0 * f0a.x; acc0.y += w0 * f0a.y; acc0.z += w0 * f0b.x; acc0.w += w0 * f0b.y;
        }
    }
#pragma unroll
    for (int o = 16; o; o >>= 1) den += __shfl_xor_sync(0xffffffffu, den, o);
    float inv = 1.0f / den;

    float b0 = bias[4 * lane + 0], b1 = bias[4 * lane + 1];
    float b2 = bias[4 * lane + 2], b3 = bias[4 * lane + 3];
    float4 v = make_float4((acc0.x + acc1.x) * inv + b0,
                           (acc0.y + acc1.y) * inv + b1,
                           (acc0.z + acc1.z) * inv + b2,
                           (acc0.w + acc1.w) * inv + b3);
    if (RELU_OUT) {
        v.x = fmaxf(v.x, 0.f); v.y = fmaxf(v.y, 0.f);
        v.z = fmaxf(v.z, 0.f); v.w = fmaxf(v.w, 0.f);
    }
    g_t4[w * 32 + lane] = v;
}

// ============================ launch (2-stream fork/join) ============================
extern "C" void kernel_launch(void* const* d_in, const int* in_sizes, int n_in,
                              void* d_out, int out_size) {
    const float* x   = (const float*)d_in[0];
    const int*   ei  = (const int*)d_in[1];     // int32 (JAX x64-disabled)
    const float* W1  = (const float*)d_in[2];
    const float* a1s = (const float*)d_in[3];
    const float* a1d = (const float*)d_in[4];
    const float* b1  = (const float*)d_in[5];
    const float* W2  = (const float*)d_in[6];
    const float* a2s = (const float*)d_in[7];
    const float* a2d = (const float*)d_in[8];
    const float* b2  = (const float*)d_in[9];
    const float* fcw = (const float*)d_in[10];
    const float* fcb = (const float*)d_in[11];
    float*       out = (float*)d_out;
    int E = in_sizes[1] / 2;
    int E4 = (E + 3) / 4;

    int gemm_blocks = (NN + 63) / 64;
    int agg_blocks  = (NN * 32 + 255) / 256;

    // side stream + events (host-side handles only; few calls, leak harmless)
    cudaStream_t s2;
    cudaStreamCreateWithFlags(&s2, cudaStreamNonBlocking);
    cudaEvent_t evFork, evJoin;
    cudaEventCreateWithFlags(&evFork, cudaEventDisableTiming);
    cudaEventCreateWithFlags(&evJoin, cudaEventDisableTiming);

    // fork: CSR chain on s2 concurrent with gemm0
    cudaEventRecord(evFork, 0);
    cudaStreamWaitEvent(s2, evFork, 0);

    k_count<<<(E4 + 255) / 256, 256, 0, s2>>>(ei, E);
    k_blocksum<<<NBLK, 1024, 0, s2>>>();
    k_top<<<1, 32, 0, s2>>>();
    k_emit<<<NBLK, 1024, 0, s2>>>();
    k_scatter<<<(E4 + 255) / 256, 256, 0, s2>>>(ei, E);
    cudaEventRecord(evJoin, s2);

    // main stream: layer-1 GEMM (independent of CSR)
    gemm_kernel<0><<<gemm_blocks, 256>>>((const float4*)x, W1, a1s, a1d);

    // join: agg1 needs both CSR and gemm0
    cudaStreamWaitEvent(0, evJoin, 0);
    agg_kernel<true><<<agg_blocks, 256>>>(b1);   // relu fused into output
    // layer 2 (input already relu'd)
    gemm_kernel<1><<<gemm_blocks, 256>>>(nullptr, W2, a2s, a2d);
    agg_kernel<false><<<agg_blocks, 256>>>(b2);
    // output head (64-col tile)
    gemm_out<<<gemm_blocks, 256>>>(fcw, fcb, out);
}